// round 5
// baseline (speedup 1.0000x reference)
#include <cuda_runtime.h>
#include <math.h>

// Problem dimensions (fixed by the dataset)
#define NN   2
#define NV   4096
#define NF   2048
#define NT   4096
#define TEXD 1024
#define HH   512
#define WW   512
#define EPSF 1e-8f
#define BIGF 1e30f

// Scratch (no allocations allowed)
__device__ float              g_vpix[NN * NV * 3];     // projected verts (x,y,z)
__device__ float              g_tri [NN * NF * 16];    // per-tri precomp
__device__ float              g_zm2 [NN * NF];         // max(z2, eps)
__device__ int4               g_bbox[NN * NF];         // clamped int bbox
__device__ unsigned long long g_key [NN * HH * WW];    // packed (depth_bits<<32 | tri_idx)

// ---------------------------------------------------------------------------
// 1) Project vertices: v_cam = R (v - campos); v_pix = focal*(xy/z)+princpt, z
// ---------------------------------------------------------------------------
__global__ void k_project(const float* __restrict__ v,
                          const float* __restrict__ campos,
                          const float* __restrict__ camrot,
                          const float* __restrict__ focal,
                          const float* __restrict__ princpt)
{
    int i = blockIdx.x * blockDim.x + threadIdx.x;
    if (i >= NN * NV) return;
    int n = i / NV;
    const float* vv = v + i * 3;
    float dx = __fsub_rn(vv[0], campos[n * 3 + 0]);
    float dy = __fsub_rn(vv[1], campos[n * 3 + 1]);
    float dz = __fsub_rn(vv[2], campos[n * 3 + 2]);
    const float* R = camrot + n * 9;
    float cx = __fadd_rn(__fadd_rn(__fmul_rn(R[0], dx), __fmul_rn(R[1], dy)), __fmul_rn(R[2], dz));
    float cy = __fadd_rn(__fadd_rn(__fmul_rn(R[3], dx), __fmul_rn(R[4], dy)), __fmul_rn(R[5], dz));
    float cz = __fadd_rn(__fadd_rn(__fmul_rn(R[6], dx), __fmul_rn(R[7], dy)), __fmul_rn(R[8], dz));
    float zm = fmaxf(cz, EPSF);
    float xz = __fdiv_rn(cx, zm);
    float yz = __fdiv_rn(cy, zm);
    const float* Fm = focal + n * 4;
    float sx = __fadd_rn(__fmul_rn(Fm[0], xz), __fmul_rn(Fm[1], yz));
    float sy = __fadd_rn(__fmul_rn(Fm[2], xz), __fmul_rn(Fm[3], yz));
    g_vpix[i * 3 + 0] = __fadd_rn(sx, princpt[n * 2 + 0]);
    g_vpix[i * 3 + 1] = __fadd_rn(sy, princpt[n * 2 + 1]);
    g_vpix[i * 3 + 2] = cz;
}

// ---------------------------------------------------------------------------
// 2) Per-triangle setup. area computed in XLA's contracted form:
//      area = fma(x2-x0, y1-y0, -((y2-y0)*(x1-x0)))
// ---------------------------------------------------------------------------
__global__ void k_trisetup(const int* __restrict__ vi)
{
    int i = blockIdx.x * blockDim.x + threadIdx.x;
    if (i >= NN * NF) return;
    int n = i / NF;
    int f = i % NF;
    int ia = vi[f * 3 + 0], ib = vi[f * 3 + 1], ic = vi[f * 3 + 2];
    const float* p = g_vpix + n * NV * 3;
    float x0 = p[ia * 3 + 0], y0 = p[ia * 3 + 1], z0 = p[ia * 3 + 2];
    float x1 = p[ib * 3 + 0], y1 = p[ib * 3 + 1], z1 = p[ib * 3 + 2];
    float x2 = p[ic * 3 + 0], y2 = p[ic * 3 + 1], z2 = p[ic * 3 + 2];

    float e0x = __fsub_rn(x2, x1), e0y = __fsub_rn(y2, y1);   // edge w0 anchor (x1,y1)
    float e1x = __fsub_rn(x0, x2), e1y = __fsub_rn(y0, y2);   // edge w1 anchor (x2,y2)
    float e2x = __fsub_rn(x1, x0), e2y = __fsub_rn(y1, y0);   // edge w2 anchor (x0,y0)
    // area = _edge(x0,y0, x1,y1, x2,y2), contracted (fma) form
    float area = __fmaf_rn(__fsub_rn(x2, x0), e2y,
                           -__fmul_rn(__fsub_rn(y2, y0), e2x));

    bool valid = (fabsf(area) > EPSF) && (z0 > EPSF) && (z1 > EPSF) && (z2 > EPSF);
    float sa = (fabsf(area) > EPSF) ? area : 1.0f;

    float* r = g_tri + i * 16;
    r[0]  = x1;  r[1]  = y1;  r[2]  = e0x; r[3]  = e0y;
    r[4]  = x2;  r[5]  = y2;  r[6]  = e1x; r[7]  = e1y;
    r[8]  = x0;  r[9]  = y0;  r[10] = e2x; r[11] = e2y;
    r[12] = area;
    r[13] = fmaxf(z0, EPSF);
    r[14] = fmaxf(z1, EPSF);
    r[15] = sa;
    g_zm2[i] = fmaxf(z2, EPSF);

    int4 bb;
    if (!valid) {
        bb.x = 1; bb.y = 0; bb.z = 1; bb.w = 0;  // empty
    } else {
        float mnx = fminf(fminf(x0, x1), x2), mxx = fmaxf(fmaxf(x0, x1), x2);
        float mny = fminf(fminf(y0, y1), y2), mxy = fmaxf(fmaxf(y0, y1), y2);
        bb.x = max(0,      (int)floorf(mnx) - 1);
        bb.y = min(WW - 1, (int)ceilf (mxx) + 1);
        bb.z = max(0,      (int)floorf(mny) - 1);
        bb.w = min(HH - 1, (int)ceilf (mxy) + 1);
        if (bb.x > bb.y || bb.z > bb.w) { bb.x = 1; bb.y = 0; bb.z = 1; bb.w = 0; }
    }
    g_bbox[i] = bb;
}

// ---------------------------------------------------------------------------
// 3) Init depth keys
// ---------------------------------------------------------------------------
__global__ void k_init()
{
    int i = blockIdx.x * blockDim.x + threadIdx.x;
    if (i < NN * HH * WW) g_key[i] = 0xFFFFFFFFFFFFFFFFULL;
}

// ---------------------------------------------------------------------------
// 4) Triangle-parallel raster. Edge functions in XLA's contracted form:
//      w = fma(px - ax, ey, -((py - ay) * ex))
//    Depth via the exact reference division chain; packed atomicMin gives
//    (min d, tie -> min index), matching the scan.
// ---------------------------------------------------------------------------
__global__ void __launch_bounds__(128, 8) k_raster()
{
    int bid = blockIdx.x;            // n*NF + f
    int4 bb = g_bbox[bid];
    if (bb.x > bb.y) return;
    int n = bid / NF;
    unsigned f = (unsigned)(bid % NF);

    const float* r = g_tri + bid * 16;
    float ax0 = r[0],  ay0 = r[1],  e0x = r[2],  e0y = r[3];
    float ax1 = r[4],  ay1 = r[5],  e1x = r[6],  e1y = r[7];
    float ax2 = r[8],  ay2 = r[9],  e2x = r[10], e2y = r[11];
    float area = r[12], zm0 = r[13], zm1 = r[14], sa = r[15];
    float zm2 = g_zm2[bid];

    unsigned long long* keys = g_key + n * HH * WW;

    for (int y = bb.z; y <= bb.w; ++y) {
        float py = (float)y;
        // row-constant second products: (py - ay)*ex  (plain mul, as XLA emits)
        float t0 = __fmul_rn(__fsub_rn(py, ay0), e0x);
        float t1 = __fmul_rn(__fsub_rn(py, ay1), e1x);
        float t2 = __fmul_rn(__fsub_rn(py, ay2), e2x);
        unsigned long long* rowk = keys + y * WW;
        for (int x = bb.x + (int)threadIdx.x; x <= bb.y; x += 128) {
            float px = (float)x;
            float w0 = __fmaf_rn(__fsub_rn(px, ax0), e0y, -t0);
            if (__fmul_rn(w0, area) < 0.0f) continue;
            float w1 = __fmaf_rn(__fsub_rn(px, ax1), e1y, -t1);
            if (__fmul_rn(w1, area) < 0.0f) continue;
            float w2 = __fmaf_rn(__fsub_rn(px, ax2), e2y, -t2);
            if (__fmul_rn(w2, area) < 0.0f) continue;
            // exact reference arithmetic for the depth key
            float a0 = __fdiv_rn(__fdiv_rn(w0, sa), zm0);
            float a1 = __fdiv_rn(__fdiv_rn(w1, sa), zm1);
            float a2 = __fdiv_rn(__fdiv_rn(w2, sa), zm2);
            float zi = __fadd_rn(__fadd_rn(a0, a1), a2);
            if (zi > EPSF) {
                float d = __fdiv_rn(1.0f, fmaxf(zi, EPSF));
                unsigned long long key =
                    ((unsigned long long)__float_as_uint(d) << 32) | (unsigned long long)f;
                atomicMin(&rowk[x], key);
            }
        }
    }
}

// ---------------------------------------------------------------------------
// 5) Decode + interpolation + texture sample + write all 6 outputs (float32)
//    Output layout (concatenated, reference tuple order):
//      render  (N,3,H,W) | mask (N,H,W) | depth (N,H,W) |
//      vt_img  (N,H,W,2) | bary (N,3,H,W) | index (N,H,W)
// ---------------------------------------------------------------------------
__global__ void k_interp(const float* __restrict__ tex,
                         const float* __restrict__ vt,
                         const int*   __restrict__ vi,
                         const int*   __restrict__ vti,
                         float* __restrict__ out)
{
    const int HW = HH * WW;
    const long long OFF_R  = 0;
    const long long OFF_M  = OFF_R  + (long long)NN * 3 * HW;
    const long long OFF_D  = OFF_M  + (long long)NN * HW;
    const long long OFF_VT = OFF_D  + (long long)NN * HW;
    const long long OFF_B  = OFF_VT + (long long)NN * HW * 2;
    const long long OFF_I  = OFF_B  + (long long)NN * 3 * HW;

    int i = blockIdx.x * blockDim.x + threadIdx.x;
    if (i >= NN * HW) return;
    int n  = i / HW;
    int hw = i % HW;
    int h  = hw / WW;
    int w  = hw % WW;

    unsigned long long key = g_key[i];
    if (key == 0xFFFFFFFFFFFFFFFFULL) {
        out[OFF_M + i] = 0.0f;
        out[OFF_D + i] = 0.0f;
        out[OFF_VT + (long long)i * 2 + 0] = 0.0f;
        out[OFF_VT + (long long)i * 2 + 1] = 0.0f;
        #pragma unroll
        for (int c = 0; c < 3; ++c) {
            out[OFF_R + (long long)(n * 3 + c) * HW + hw] = 0.0f;
            out[OFF_B + (long long)(n * 3 + c) * HW + hw] = 0.0f;
        }
        out[OFF_I + i] = -1.0f;
        return;
    }
    int idx = (int)(unsigned)(key & 0xFFFFFFFFULL);

    const float* p = g_vpix + n * NV * 3;
    int ia = vi[idx * 3 + 0], ib = vi[idx * 3 + 1], ic = vi[idx * 3 + 2];
    float x0 = p[ia * 3 + 0], y0 = p[ia * 3 + 1], z0 = p[ia * 3 + 2];
    float x1 = p[ib * 3 + 0], y1 = p[ib * 3 + 1], z1 = p[ib * 3 + 2];
    float x2 = p[ic * 3 + 0], y2 = p[ic * 3 + 1], z2 = p[ic * 3 + 2];

    float px = (float)w, py = (float)h;
    // contracted (fma) edge functions, matching XLA
    float w0 = __fmaf_rn(__fsub_rn(px, x1), __fsub_rn(y2, y1),
                         -__fmul_rn(__fsub_rn(py, y1), __fsub_rn(x2, x1)));
    float w1 = __fmaf_rn(__fsub_rn(px, x2), __fsub_rn(y0, y2),
                         -__fmul_rn(__fsub_rn(py, y2), __fsub_rn(x0, x2)));
    float w2 = __fmaf_rn(__fsub_rn(px, x0), __fsub_rn(y1, y0),
                         -__fmul_rn(__fsub_rn(py, y0), __fsub_rn(x1, x0)));
    float area = __fmaf_rn(__fsub_rn(x2, x0), __fsub_rn(y1, y0),
                           -__fmul_rn(__fsub_rn(y2, y0), __fsub_rn(x1, x0)));
    float sa = (fabsf(area) > EPSF) ? area : 1.0f;
    float b0 = __fdiv_rn(w0, sa);
    float b1 = __fdiv_rn(w1, sa);
    float b2 = __fdiv_rn(w2, sa);
    float bz0 = __fdiv_rn(b0, fmaxf(z0, EPSF));
    float bz1 = __fdiv_rn(b1, fmaxf(z1, EPSF));
    float bz2 = __fdiv_rn(b2, fmaxf(z2, EPSF));
    float zi = fmaxf(__fadd_rn(__fadd_rn(bz0, bz1), bz2), EPSF);
    float bary0 = __fdiv_rn(bz0, zi);
    float bary1 = __fdiv_rn(bz1, zi);
    float bary2 = __fdiv_rn(bz2, zi);
    float depth = __fdiv_rn(1.0f, zi);

    int ta = vti[idx * 3 + 0], tb = vti[idx * 3 + 1], tc = vti[idx * 3 + 2];
    float u0 = vt[ta * 2 + 0], v0 = __fsub_rn(1.0f, vt[ta * 2 + 1]);
    float u1 = vt[tb * 2 + 0], v1 = __fsub_rn(1.0f, vt[tb * 2 + 1]);
    float u2 = vt[tc * 2 + 0], v2 = __fsub_rn(1.0f, vt[tc * 2 + 1]);
    float vtu = __fadd_rn(__fadd_rn(__fmul_rn(bary0, u0), __fmul_rn(bary1, u1)), __fmul_rn(bary2, u2));
    float vtv = __fadd_rn(__fadd_rn(__fmul_rn(bary0, v0), __fmul_rn(bary1, v1)), __fmul_rn(bary2, v2));

    // grid sample (border padding, bilinear) on (N,3,1024,1024)
    float gx = __fsub_rn(__fmul_rn(vtu, 2.0f), 1.0f);
    float gy = __fsub_rn(__fmul_rn(vtv, 2.0f), 1.0f);
    float ix = (gx + 1.0f) * 0.5f * (float)TEXD - 0.5f;
    float iy = (gy + 1.0f) * 0.5f * (float)TEXD - 0.5f;
    float x0f = floorf(ix), y0f = floorf(iy);
    float fx = ix - x0f, fy = iy - y0f;
    int x0i = min(max((int)x0f, 0), TEXD - 1);
    int x1i = min(max((int)x0f + 1, 0), TEXD - 1);
    int y0i = min(max((int)y0f, 0), TEXD - 1);
    int y1i = min(max((int)y0f + 1, 0), TEXD - 1);

    #pragma unroll
    for (int c = 0; c < 3; ++c) {
        const float* tb_ = tex + ((long long)(n * 3 + c) * TEXD) * TEXD;
        float v00 = tb_[y0i * TEXD + x0i];
        float v01 = tb_[y0i * TEXD + x1i];
        float v10 = tb_[y1i * TEXD + x0i];
        float v11 = tb_[y1i * TEXD + x1i];
        float top = v00 * (1.0f - fx) + v01 * fx;
        float bot = v10 * (1.0f - fx) + v11 * fx;
        float val = top * (1.0f - fy) + bot * fy;
        out[OFF_R + (long long)(n * 3 + c) * HW + hw] = val;
    }

    out[OFF_M + i] = 1.0f;
    out[OFF_D + i] = depth;
    out[OFF_VT + (long long)i * 2 + 0] = vtu;
    out[OFF_VT + (long long)i * 2 + 1] = vtv;
    out[OFF_B + (long long)(n * 3 + 0) * HW + hw] = bary0;
    out[OFF_B + (long long)(n * 3 + 1) * HW + hw] = bary1;
    out[OFF_B + (long long)(n * 3 + 2) * HW + hw] = bary2;
    out[OFF_I + i] = (float)idx;
}

// ---------------------------------------------------------------------------
extern "C" void kernel_launch(void* const* d_in, const int* in_sizes, int n_in,
                              void* d_out, int out_size)
{
    const float* v       = (const float*)d_in[0];
    const float* tex     = (const float*)d_in[1];
    const float* vt      = (const float*)d_in[2];
    const int*   vi      = (const int*)  d_in[3];
    const int*   vti     = (const int*)  d_in[4];
    const float* campos  = (const float*)d_in[5];
    const float* camrot  = (const float*)d_in[6];
    const float* focal   = (const float*)d_in[7];
    const float* princpt = (const float*)d_in[8];
    float* out = (float*)d_out;

    k_project<<<(NN * NV + 255) / 256, 256>>>(v, campos, camrot, focal, princpt);
    k_trisetup<<<(NN * NF + 255) / 256, 256>>>(vi);
    k_init<<<(NN * HH * WW + 255) / 256, 256>>>();
    k_raster<<<NN * NF, 128>>>();
    k_interp<<<(NN * HH * WW + 255) / 256, 256>>>(tex, vt, vi, vti, out);
}

// round 9
// speedup vs baseline: 1.3522x; 1.3522x over previous
#include <cuda_runtime.h>
#include <math.h>

// Problem dimensions (fixed by the dataset)
#define NN   2
#define NV   4096
#define NF   2048
#define NT   4096
#define TEXD 1024
#define HH   512
#define WW   512
#define EPSF 1e-8f
#define BIGF 1e30f

// Scratch (no allocations allowed)
__device__ float              g_vpix[NN * NV * 3];     // projected verts (x,y,z)
__device__ float              g_tri [NN * NF * 16];    // per-tri precomp (sign-folded)
__device__ int4               g_bbox[NN * NF];         // clamped int bbox
__device__ unsigned long long g_key [NN * HH * WW];    // packed (d_bits<<32 | tri), atomicMin

// ---------------------------------------------------------------------------
// 1) Project vertices
// ---------------------------------------------------------------------------
__global__ void k_project(const float* __restrict__ v,
                          const float* __restrict__ campos,
                          const float* __restrict__ camrot,
                          const float* __restrict__ focal,
                          const float* __restrict__ princpt)
{
    int i = blockIdx.x * blockDim.x + threadIdx.x;
    if (i >= NN * NV) return;
    int n = i / NV;
    const float* vv = v + i * 3;
    float dx = __fsub_rn(vv[0], campos[n * 3 + 0]);
    float dy = __fsub_rn(vv[1], campos[n * 3 + 1]);
    float dz = __fsub_rn(vv[2], campos[n * 3 + 2]);
    const float* R = camrot + n * 9;
    float cx = __fadd_rn(__fadd_rn(__fmul_rn(R[0], dx), __fmul_rn(R[1], dy)), __fmul_rn(R[2], dz));
    float cy = __fadd_rn(__fadd_rn(__fmul_rn(R[3], dx), __fmul_rn(R[4], dy)), __fmul_rn(R[5], dz));
    float cz = __fadd_rn(__fadd_rn(__fmul_rn(R[6], dx), __fmul_rn(R[7], dy)), __fmul_rn(R[8], dz));
    float zm = fmaxf(cz, EPSF);
    float xz = __fdiv_rn(cx, zm);
    float yz = __fdiv_rn(cy, zm);
    const float* Fm = focal + n * 4;
    float sx = __fadd_rn(__fmul_rn(Fm[0], xz), __fmul_rn(Fm[1], yz));
    float sy = __fadd_rn(__fmul_rn(Fm[2], xz), __fmul_rn(Fm[3], yz));
    g_vpix[i * 3 + 0] = __fadd_rn(sx, princpt[n * 2 + 0]);
    g_vpix[i * 3 + 1] = __fadd_rn(sy, princpt[n * 2 + 1]);
    g_vpix[i * 3 + 2] = cz;
}

// ---------------------------------------------------------------------------
// 2) Per-triangle setup. Edge coeffs sign-folded by s = sign(area) so the
//    inside test is w' >= 0 (bitwise equiv to w*area >= 0). For the depth:
//    (w'/|sa|)/zm == (w/sa)/zm bitwise (correctly-rounded div of identical
//    real quotient), so we store saq = |sa| and zm0..2.
// ---------------------------------------------------------------------------
__global__ void k_trisetup(const int* __restrict__ vi)
{
    int i = blockIdx.x * blockDim.x + threadIdx.x;
    if (i >= NN * NF) return;
    int n = i / NF;
    int f = i % NF;
    int ia = vi[f * 3 + 0], ib = vi[f * 3 + 1], ic = vi[f * 3 + 2];
    const float* p = g_vpix + n * NV * 3;
    float x0 = p[ia * 3 + 0], y0 = p[ia * 3 + 1], z0 = p[ia * 3 + 2];
    float x1 = p[ib * 3 + 0], y1 = p[ib * 3 + 1], z1 = p[ib * 3 + 2];
    float x2 = p[ic * 3 + 0], y2 = p[ic * 3 + 1], z2 = p[ic * 3 + 2];

    float e0x = __fsub_rn(x2, x1), e0y = __fsub_rn(y2, y1);   // edge w0 anchor (x1,y1)
    float e1x = __fsub_rn(x0, x2), e1y = __fsub_rn(y0, y2);   // edge w1 anchor (x2,y2)
    float e2x = __fsub_rn(x1, x0), e2y = __fsub_rn(y1, y0);   // edge w2 anchor (x0,y0)
    // area in XLA's contracted (fma) form
    float area = __fmaf_rn(__fsub_rn(x2, x0), e2y,
                           -__fmul_rn(__fsub_rn(y2, y0), e2x));

    bool valid = (fabsf(area) > EPSF) && (z0 > EPSF) && (z1 > EPSF) && (z2 > EPSF);
    float s = (area < 0.0f) ? -1.0f : 1.0f;   // exact sign fold
    float saq = fabsf(area);                   // |sa| (valid path only; else bbox empty)

    float* r = g_tri + i * 16;
    r[0]  = x1;  r[1]  = y1;  r[2]  = s * e0x; r[3]  = s * e0y;
    r[4]  = x2;  r[5]  = y2;  r[6]  = s * e1x; r[7]  = s * e1y;
    r[8]  = x0;  r[9]  = y0;  r[10] = s * e2x; r[11] = s * e2y;
    r[12] = saq;
    r[13] = fmaxf(z0, EPSF);
    r[14] = fmaxf(z1, EPSF);
    r[15] = fmaxf(z2, EPSF);

    int4 bb;
    if (!valid) {
        bb.x = 1; bb.y = 0; bb.z = 1; bb.w = 0;  // empty
    } else {
        float mnx = fminf(fminf(x0, x1), x2), mxx = fmaxf(fmaxf(x0, x1), x2);
        float mny = fminf(fminf(y0, y1), y2), mxy = fmaxf(fmaxf(y0, y1), y2);
        bb.x = max(0,      (int)floorf(mnx) - 1);
        bb.y = min(WW - 1, (int)ceilf (mxx) + 1);
        bb.z = max(0,      (int)floorf(mny) - 1);
        bb.w = min(HH - 1, (int)ceilf (mxy) + 1);
        if (bb.x > bb.y || bb.z > bb.w) { bb.x = 1; bb.y = 0; bb.z = 1; bb.w = 0; }
    }
    g_bbox[i] = bb;
}

// ---------------------------------------------------------------------------
// 3) Init keys (atomicMin accumulates)
// ---------------------------------------------------------------------------
__global__ void k_init()
{
    int i = blockIdx.x * blockDim.x + threadIdx.x;
    if (i < NN * HH * WW) g_key[i] = 0xFFFFFFFFFFFFFFFFULL;
}

// ---------------------------------------------------------------------------
// 4) Triangle-parallel raster. One block per (n,f); warp per row (y += 4),
//    lanes stride x by 32 within a conservatively clipped row span.
//    Exact FMA edge tests decide; span clip only skips provably-outside x.
//    Depth via the EXACT reference division chain:
//      a_k = ((w'_k)/|sa|)/zm_k   (bitwise == (w_k/sa)/zm_k)
//      zi  = (a0 + a1) + a2 ; d = 1/max(zi,eps) if zi > eps
//    Key = (d_bits<<32)|f under atomicMin == (min depth, tie -> min index).
// ---------------------------------------------------------------------------
__global__ void __launch_bounds__(128, 8) k_raster()
{
    int bid = blockIdx.x;            // n*NF + f
    int4 bb = g_bbox[bid];
    if (bb.x > bb.y) return;
    int n = bid / NF;
    unsigned f = (unsigned)(bid % NF);

    const float* r = g_tri + bid * 16;
    float ax0 = r[0],  ay0 = r[1],  e0x = r[2],  e0y = r[3];
    float ax1 = r[4],  ay1 = r[5],  e1x = r[6],  e1y = r[7];
    float ax2 = r[8],  ay2 = r[9],  e2x = r[10], e2y = r[11];
    float saq = r[12], zm0 = r[13], zm1 = r[14], zm2 = r[15];

    unsigned long long* keys = g_key + n * HH * WW;

    int warp = (int)(threadIdx.x >> 5);
    int lane = (int)(threadIdx.x & 31);

    for (int y = bb.z + warp; y <= bb.w; y += 4) {
        float py = (float)y;
        // row-constant second products (plain mul, matching XLA form)
        float t0 = __fmul_rn(__fsub_rn(py, ay0), e0x);
        float t1 = __fmul_rn(__fsub_rn(py, ay1), e1x);
        float t2 = __fmul_rn(__fsub_rn(py, ay2), e2x);

        // conservative row span from edge-line roots (exact tests still decide)
        float xlo = (float)bb.x, xhi = (float)bb.y;
        {
            if (fabsf(e0y) * 8192.0f > fabsf(e0x)) {
                float rt = __fmaf_rn(t0, __frcp_rn(e0y), ax0);
                if (e0y > 0.0f) xlo = fmaxf(xlo, rt - 2.0f);
                else            xhi = fminf(xhi, rt + 2.0f);
            }
            if (fabsf(e1y) * 8192.0f > fabsf(e1x)) {
                float rt = __fmaf_rn(t1, __frcp_rn(e1y), ax1);
                if (e1y > 0.0f) xlo = fmaxf(xlo, rt - 2.0f);
                else            xhi = fminf(xhi, rt + 2.0f);
            }
            if (fabsf(e2y) * 8192.0f > fabsf(e2x)) {
                float rt = __fmaf_rn(t2, __frcp_rn(e2y), ax2);
                if (e2y > 0.0f) xlo = fmaxf(xlo, rt - 2.0f);
                else            xhi = fminf(xhi, rt + 2.0f);
            }
        }
        int ixlo = max(bb.x, (int)floorf(xlo));
        int ixhi = min(bb.y, (int)ceilf(xhi));

        unsigned long long* rowk = keys + y * WW;
        for (int x = ixlo + lane; x <= ixhi; x += 32) {
            float px = (float)x;
            float w0 = __fmaf_rn(__fsub_rn(px, ax0), e0y, -t0);
            float w1 = __fmaf_rn(__fsub_rn(px, ax1), e1y, -t1);
            float w2 = __fmaf_rn(__fsub_rn(px, ax2), e2y, -t2);
            if (w0 >= 0.0f && w1 >= 0.0f && w2 >= 0.0f) {
                // exact reference arithmetic for the depth key
                float a0 = __fdiv_rn(__fdiv_rn(w0, saq), zm0);
                float a1 = __fdiv_rn(__fdiv_rn(w1, saq), zm1);
                float a2 = __fdiv_rn(__fdiv_rn(w2, saq), zm2);
                float zi = __fadd_rn(__fadd_rn(a0, a1), a2);
                if (zi > EPSF) {
                    float d = __fdiv_rn(1.0f, fmaxf(zi, EPSF));
                    unsigned long long key =
                        ((unsigned long long)__float_as_uint(d) << 32) | (unsigned long long)f;
                    atomicMin(&rowk[x], key);
                }
            }
        }
    }
}

// ---------------------------------------------------------------------------
// 5) Decode + interpolation + texture sample + write all 6 outputs (float32)
//    Output layout (concatenated, reference tuple order):
//      render  (N,3,H,W) | mask (N,H,W) | depth (N,H,W) |
//      vt_img  (N,H,W,2) | bary (N,3,H,W) | index (N,H,W)
// ---------------------------------------------------------------------------
__global__ void k_interp(const float* __restrict__ tex,
                         const float* __restrict__ vt,
                         const int*   __restrict__ vi,
                         const int*   __restrict__ vti,
                         float* __restrict__ out)
{
    const int HW = HH * WW;
    const long long OFF_R  = 0;
    const long long OFF_M  = OFF_R  + (long long)NN * 3 * HW;
    const long long OFF_D  = OFF_M  + (long long)NN * HW;
    const long long OFF_VT = OFF_D  + (long long)NN * HW;
    const long long OFF_B  = OFF_VT + (long long)NN * HW * 2;
    const long long OFF_I  = OFF_B  + (long long)NN * 3 * HW;

    int i = blockIdx.x * blockDim.x + threadIdx.x;
    if (i >= NN * HW) return;
    int n  = i / HW;
    int hw = i % HW;
    int h  = hw / WW;
    int w  = hw % WW;

    unsigned long long key = g_key[i];
    if (key == 0xFFFFFFFFFFFFFFFFULL) {
        out[OFF_M + i] = 0.0f;
        out[OFF_D + i] = 0.0f;
        out[OFF_VT + (long long)i * 2 + 0] = 0.0f;
        out[OFF_VT + (long long)i * 2 + 1] = 0.0f;
        #pragma unroll
        for (int c = 0; c < 3; ++c) {
            out[OFF_R + (long long)(n * 3 + c) * HW + hw] = 0.0f;
            out[OFF_B + (long long)(n * 3 + c) * HW + hw] = 0.0f;
        }
        out[OFF_I + i] = -1.0f;
        return;
    }
    int idx = (int)(unsigned)(key & 0xFFFFFFFFULL);

    const float* p = g_vpix + n * NV * 3;
    int ia = vi[idx * 3 + 0], ib = vi[idx * 3 + 1], ic = vi[idx * 3 + 2];
    float x0 = p[ia * 3 + 0], y0 = p[ia * 3 + 1], z0 = p[ia * 3 + 2];
    float x1 = p[ib * 3 + 0], y1 = p[ib * 3 + 1], z1 = p[ib * 3 + 2];
    float x2 = p[ic * 3 + 0], y2 = p[ic * 3 + 1], z2 = p[ic * 3 + 2];

    float px = (float)w, py = (float)h;
    // contracted (fma) edge functions, matching XLA
    float w0 = __fmaf_rn(__fsub_rn(px, x1), __fsub_rn(y2, y1),
                         -__fmul_rn(__fsub_rn(py, y1), __fsub_rn(x2, x1)));
    float w1 = __fmaf_rn(__fsub_rn(px, x2), __fsub_rn(y0, y2),
                         -__fmul_rn(__fsub_rn(py, y2), __fsub_rn(x0, x2)));
    float w2 = __fmaf_rn(__fsub_rn(px, x0), __fsub_rn(y1, y0),
                         -__fmul_rn(__fsub_rn(py, y0), __fsub_rn(x1, x0)));
    float area = __fmaf_rn(__fsub_rn(x2, x0), __fsub_rn(y1, y0),
                           -__fmul_rn(__fsub_rn(y2, y0), __fsub_rn(x1, x0)));
    float sa = (fabsf(area) > EPSF) ? area : 1.0f;
    float b0 = __fdiv_rn(w0, sa);
    float b1 = __fdiv_rn(w1, sa);
    float b2 = __fdiv_rn(w2, sa);
    float bz0 = __fdiv_rn(b0, fmaxf(z0, EPSF));
    float bz1 = __fdiv_rn(b1, fmaxf(z1, EPSF));
    float bz2 = __fdiv_rn(b2, fmaxf(z2, EPSF));
    float zi = fmaxf(__fadd_rn(__fadd_rn(bz0, bz1), bz2), EPSF);
    float bary0 = __fdiv_rn(bz0, zi);
    float bary1 = __fdiv_rn(bz1, zi);
    float bary2 = __fdiv_rn(bz2, zi);
    float depth = __fdiv_rn(1.0f, zi);

    int ta = vti[idx * 3 + 0], tb = vti[idx * 3 + 1], tc = vti[idx * 3 + 2];
    float u0 = vt[ta * 2 + 0], v0 = __fsub_rn(1.0f, vt[ta * 2 + 1]);
    float u1 = vt[tb * 2 + 0], v1 = __fsub_rn(1.0f, vt[tb * 2 + 1]);
    float u2 = vt[tc * 2 + 0], v2 = __fsub_rn(1.0f, vt[tc * 2 + 1]);
    float vtu = __fadd_rn(__fadd_rn(__fmul_rn(bary0, u0), __fmul_rn(bary1, u1)), __fmul_rn(bary2, u2));
    float vtv = __fadd_rn(__fadd_rn(__fmul_rn(bary0, v0), __fmul_rn(bary1, v1)), __fmul_rn(bary2, v2));

    // grid sample (border padding, bilinear) on (N,3,1024,1024)
    float gx = __fsub_rn(__fmul_rn(vtu, 2.0f), 1.0f);
    float gy = __fsub_rn(__fmul_rn(vtv, 2.0f), 1.0f);
    float ix = (gx + 1.0f) * 0.5f * (float)TEXD - 0.5f;
    float iy = (gy + 1.0f) * 0.5f * (float)TEXD - 0.5f;
    float x0f = floorf(ix), y0f = floorf(iy);
    float fx = ix - x0f, fy = iy - y0f;
    int x0i = min(max((int)x0f, 0), TEXD - 1);
    int x1i = min(max((int)x0f + 1, 0), TEXD - 1);
    int y0i = min(max((int)y0f, 0), TEXD - 1);
    int y1i = min(max((int)y0f + 1, 0), TEXD - 1);

    #pragma unroll
    for (int c = 0; c < 3; ++c) {
        const float* tb_ = tex + ((long long)(n * 3 + c) * TEXD) * TEXD;
        float v00 = tb_[y0i * TEXD + x0i];
        float v01 = tb_[y0i * TEXD + x1i];
        float v10 = tb_[y1i * TEXD + x0i];
        float v11 = tb_[y1i * TEXD + x1i];
        float top = v00 * (1.0f - fx) + v01 * fx;
        float bot = v10 * (1.0f - fx) + v11 * fx;
        float val = top * (1.0f - fy) + bot * fy;
        out[OFF_R + (long long)(n * 3 + c) * HW + hw] = val;
    }

    out[OFF_M + i] = 1.0f;
    out[OFF_D + i] = depth;
    out[OFF_VT + (long long)i * 2 + 0] = vtu;
    out[OFF_VT + (long long)i * 2 + 1] = vtv;
    out[OFF_B + (long long)(n * 3 + 0) * HW + hw] = bary0;
    out[OFF_B + (long long)(n * 3 + 1) * HW + hw] = bary1;
    out[OFF_B + (long long)(n * 3 + 2) * HW + hw] = bary2;
    out[OFF_I + i] = (float)idx;
}

// ---------------------------------------------------------------------------
extern "C" void kernel_launch(void* const* d_in, const int* in_sizes, int n_in,
                              void* d_out, int out_size)
{
    const float* v       = (const float*)d_in[0];
    const float* tex     = (const float*)d_in[1];
    const float* vt      = (const float*)d_in[2];
    const int*   vi      = (const int*)  d_in[3];
    const int*   vti     = (const int*)  d_in[4];
    const float* campos  = (const float*)d_in[5];
    const float* camrot  = (const float*)d_in[6];
    const float* focal   = (const float*)d_in[7];
    const float* princpt = (const float*)d_in[8];
    float* out = (float*)d_out;

    k_project<<<(NN * NV + 255) / 256, 256>>>(v, campos, camrot, focal, princpt);
    k_trisetup<<<(NN * NF + 255) / 256, 256>>>(vi);
    k_init<<<(NN * HH * WW + 255) / 256, 256>>>();
    k_raster<<<NN * NF, 128>>>();
    k_interp<<<(NN * HH * WW + 255) / 256, 256>>>(tex, vt, vi, vti, out);
}

// round 10
// speedup vs baseline: 2.2316x; 1.6504x over previous
#include <cuda_runtime.h>
#include <math.h>

// Problem dimensions (fixed by the dataset)
#define NN   2
#define NV   4096
#define NF   2048
#define NT   4096
#define TEXD 1024
#define HH   512
#define WW   512
#define EPSF 1e-8f
#define BIGF 1e30f

#define YSPLIT 8   // gridDim.y row-slices per triangle

// Scratch (no allocations allowed)
__device__ float              g_vpix[NN * NV * 3];     // projected verts (x,y,z)
__device__ float              g_tri [NN * NF * 16];    // per-tri precomp (sign-folded)
__device__ float4             g_q   [NN * NF];         // approx q_k = 1/(saq*zm_k)
__device__ int4               g_bbox[NN * NF];         // clamped int bbox
__device__ unsigned long long g_key [NN * HH * WW];    // packed (d_bits<<32 | tri), atomicMin

// ---------------------------------------------------------------------------
// 1) Project vertices
// ---------------------------------------------------------------------------
__global__ void k_project(const float* __restrict__ v,
                          const float* __restrict__ campos,
                          const float* __restrict__ camrot,
                          const float* __restrict__ focal,
                          const float* __restrict__ princpt)
{
    int i = blockIdx.x * blockDim.x + threadIdx.x;
    if (i >= NN * NV) return;
    int n = i / NV;
    const float* vv = v + i * 3;
    float dx = __fsub_rn(vv[0], campos[n * 3 + 0]);
    float dy = __fsub_rn(vv[1], campos[n * 3 + 1]);
    float dz = __fsub_rn(vv[2], campos[n * 3 + 2]);
    const float* R = camrot + n * 9;
    float cx = __fadd_rn(__fadd_rn(__fmul_rn(R[0], dx), __fmul_rn(R[1], dy)), __fmul_rn(R[2], dz));
    float cy = __fadd_rn(__fadd_rn(__fmul_rn(R[3], dx), __fmul_rn(R[4], dy)), __fmul_rn(R[5], dz));
    float cz = __fadd_rn(__fadd_rn(__fmul_rn(R[6], dx), __fmul_rn(R[7], dy)), __fmul_rn(R[8], dz));
    float zm = fmaxf(cz, EPSF);
    float xz = __fdiv_rn(cx, zm);
    float yz = __fdiv_rn(cy, zm);
    const float* Fm = focal + n * 4;
    float sx = __fadd_rn(__fmul_rn(Fm[0], xz), __fmul_rn(Fm[1], yz));
    float sy = __fadd_rn(__fmul_rn(Fm[2], xz), __fmul_rn(Fm[3], yz));
    g_vpix[i * 3 + 0] = __fadd_rn(sx, princpt[n * 2 + 0]);
    g_vpix[i * 3 + 1] = __fadd_rn(sy, princpt[n * 2 + 1]);
    g_vpix[i * 3 + 2] = cz;
}

// ---------------------------------------------------------------------------
// 2) Per-triangle setup. Edge coeffs sign-folded by s = sign(area) so the
//    inside test is w' >= 0 (bitwise equiv to w*area >= 0). Exact-depth
//    operands: saq = |sa|, zm_k. Approx early-z coeffs: q_k = 1/(saq*zm_k).
// ---------------------------------------------------------------------------
__global__ void k_trisetup(const int* __restrict__ vi)
{
    int i = blockIdx.x * blockDim.x + threadIdx.x;
    if (i >= NN * NF) return;
    int n = i / NF;
    int f = i % NF;
    int ia = vi[f * 3 + 0], ib = vi[f * 3 + 1], ic = vi[f * 3 + 2];
    const float* p = g_vpix + n * NV * 3;
    float x0 = p[ia * 3 + 0], y0 = p[ia * 3 + 1], z0 = p[ia * 3 + 2];
    float x1 = p[ib * 3 + 0], y1 = p[ib * 3 + 1], z1 = p[ib * 3 + 2];
    float x2 = p[ic * 3 + 0], y2 = p[ic * 3 + 1], z2 = p[ic * 3 + 2];

    float e0x = __fsub_rn(x2, x1), e0y = __fsub_rn(y2, y1);   // edge w0 anchor (x1,y1)
    float e1x = __fsub_rn(x0, x2), e1y = __fsub_rn(y0, y2);   // edge w1 anchor (x2,y2)
    float e2x = __fsub_rn(x1, x0), e2y = __fsub_rn(y1, y0);   // edge w2 anchor (x0,y0)
    // area in XLA's contracted (fma) form
    float area = __fmaf_rn(__fsub_rn(x2, x0), e2y,
                           -__fmul_rn(__fsub_rn(y2, y0), e2x));

    bool valid = (fabsf(area) > EPSF) && (z0 > EPSF) && (z1 > EPSF) && (z2 > EPSF);
    float s = (area < 0.0f) ? -1.0f : 1.0f;   // exact sign fold
    float saq = fabsf(area);                   // |sa| (valid path only; else bbox empty)
    float zm0 = fmaxf(z0, EPSF), zm1 = fmaxf(z1, EPSF), zm2 = fmaxf(z2, EPSF);

    float* r = g_tri + i * 16;
    r[0]  = x1;  r[1]  = y1;  r[2]  = s * e0x; r[3]  = s * e0y;
    r[4]  = x2;  r[5]  = y2;  r[6]  = s * e1x; r[7]  = s * e1y;
    r[8]  = x0;  r[9]  = y0;  r[10] = s * e2x; r[11] = s * e2y;
    r[12] = saq;
    r[13] = zm0;
    r[14] = zm1;
    r[15] = zm2;

    float4 q;
    q.x = __fdiv_rn(1.0f, __fmul_rn(saq, zm0));
    q.y = __fdiv_rn(1.0f, __fmul_rn(saq, zm1));
    q.z = __fdiv_rn(1.0f, __fmul_rn(saq, zm2));
    q.w = 0.0f;
    g_q[i] = q;

    int4 bb;
    if (!valid) {
        bb.x = 1; bb.y = 0; bb.z = 1; bb.w = 0;  // empty
    } else {
        float mnx = fminf(fminf(x0, x1), x2), mxx = fmaxf(fmaxf(x0, x1), x2);
        float mny = fminf(fminf(y0, y1), y2), mxy = fmaxf(fmaxf(y0, y1), y2);
        bb.x = max(0,      (int)floorf(mnx) - 1);
        bb.y = min(WW - 1, (int)ceilf (mxx) + 1);
        bb.z = max(0,      (int)floorf(mny) - 1);
        bb.w = min(HH - 1, (int)ceilf (mxy) + 1);
        if (bb.x > bb.y || bb.z > bb.w) { bb.x = 1; bb.y = 0; bb.z = 1; bb.w = 0; }
    }
    g_bbox[i] = bb;
}

// ---------------------------------------------------------------------------
// 3) Init keys (atomicMin accumulates)
// ---------------------------------------------------------------------------
__global__ void k_init()
{
    int i = blockIdx.x * blockDim.x + threadIdx.x;
    if (i < NN * HH * WW) g_key[i] = 0xFFFFFFFFFFFFFFFFULL;
}

// ---------------------------------------------------------------------------
// 4) Triangle-parallel raster. Grid (NN*NF, YSPLIT); 4 warps per block;
//    row-stream = blockIdx.y*4 + warp, stride YSPLIT*4 rows. Lanes stride x
//    by 32 within a conservatively clipped row span.
//    Early-z: approximate depth (pos-terms FMA, rel err <~1e-6) + __ldcg of
//    the current key; skip the exact chain + atomic only when the candidate
//    provably loses (margin 1e-4, 100x the arithmetic error; NaN-init keys
//    compare false -> no skip). Winner selection itself is UNCHANGED:
//      a_k = ((w'_k)/|sa|)/zm_k  (bitwise == (w_k/sa)/zm_k)
//      zi  = (a0 + a1) + a2 ; d = 1/max(zi,eps) if zi > eps
//      atomicMin((d_bits<<32)|f) == (min depth, tie -> min index)
// ---------------------------------------------------------------------------
__global__ void __launch_bounds__(128, 8) k_raster()
{
    int bid = blockIdx.x;            // n*NF + f
    int4 bb = g_bbox[bid];
    if (bb.x > bb.y) return;
    int n = bid / NF;
    unsigned f = (unsigned)(bid % NF);

    const float* r = g_tri + bid * 16;
    float ax0 = r[0],  ay0 = r[1],  e0x = r[2],  e0y = r[3];
    float ax1 = r[4],  ay1 = r[5],  e1x = r[6],  e1y = r[7];
    float ax2 = r[8],  ay2 = r[9],  e2x = r[10], e2y = r[11];
    float saq = r[12], zm0 = r[13], zm1 = r[14], zm2 = r[15];
    float4 q = g_q[bid];

    unsigned long long* keys = g_key + n * HH * WW;

    int warp = (int)(threadIdx.x >> 5);
    int lane = (int)(threadIdx.x & 31);
    int ystream = (int)blockIdx.y * 4 + warp;     // 0 .. YSPLIT*4-1

    for (int y = bb.z + ystream; y <= bb.w; y += YSPLIT * 4) {
        float py = (float)y;
        // row-constant second products (plain mul, matching XLA form)
        float t0 = __fmul_rn(__fsub_rn(py, ay0), e0x);
        float t1 = __fmul_rn(__fsub_rn(py, ay1), e1x);
        float t2 = __fmul_rn(__fsub_rn(py, ay2), e2x);

        // conservative row span from edge-line roots (exact tests still decide)
        float xlo = (float)bb.x, xhi = (float)bb.y;
        {
            if (fabsf(e0y) * 8192.0f > fabsf(e0x)) {
                float rt = __fmaf_rn(t0, __frcp_rn(e0y), ax0);
                if (e0y > 0.0f) xlo = fmaxf(xlo, rt - 2.0f);
                else            xhi = fminf(xhi, rt + 2.0f);
            }
            if (fabsf(e1y) * 8192.0f > fabsf(e1x)) {
                float rt = __fmaf_rn(t1, __frcp_rn(e1y), ax1);
                if (e1y > 0.0f) xlo = fmaxf(xlo, rt - 2.0f);
                else            xhi = fminf(xhi, rt + 2.0f);
            }
            if (fabsf(e2y) * 8192.0f > fabsf(e2x)) {
                float rt = __fmaf_rn(t2, __frcp_rn(e2y), ax2);
                if (e2y > 0.0f) xlo = fmaxf(xlo, rt - 2.0f);
                else            xhi = fminf(xhi, rt + 2.0f);
            }
        }
        int ixlo = max(bb.x, (int)floorf(xlo));
        int ixhi = min(bb.y, (int)ceilf(xhi));

        unsigned long long* rowk = keys + y * WW;
        for (int x = ixlo + lane; x <= ixhi; x += 32) {
            float px = (float)x;
            float w0 = __fmaf_rn(__fsub_rn(px, ax0), e0y, -t0);
            float w1 = __fmaf_rn(__fsub_rn(px, ax1), e1y, -t1);
            float w2 = __fmaf_rn(__fsub_rn(px, ax2), e2y, -t2);
            if (w0 >= 0.0f && w1 >= 0.0f && w2 >= 0.0f) {
                // --- early-z prefilter (conservative; cannot change winner) ---
                float zi_fast = __fmaf_rn(w0, q.x, __fmaf_rn(w1, q.y, __fmul_rn(w2, q.z)));
                float d_approx = __frcp_rn(zi_fast);
                unsigned long long cur = __ldcg(&rowk[x]);
                float d_cur = __uint_as_float((unsigned)(cur >> 32));
                // skip iff provably worse (NaN d_cur -> compare false -> no skip)
                if (d_approx * 0.9999f > d_cur) continue;

                // --- exact reference arithmetic for the depth key ---
                float a0 = __fdiv_rn(__fdiv_rn(w0, saq), zm0);
                float a1 = __fdiv_rn(__fdiv_rn(w1, saq), zm1);
                float a2 = __fdiv_rn(__fdiv_rn(w2, saq), zm2);
                float zi = __fadd_rn(__fadd_rn(a0, a1), a2);
                if (zi > EPSF) {
                    float d = __fdiv_rn(1.0f, fmaxf(zi, EPSF));
                    unsigned long long key =
                        ((unsigned long long)__float_as_uint(d) << 32) | (unsigned long long)f;
                    atomicMin(&rowk[x], key);
                }
            }
        }
    }
}

// ---------------------------------------------------------------------------
// 5) Decode + interpolation + texture sample + write all 6 outputs (float32)
//    Output layout (concatenated, reference tuple order):
//      render  (N,3,H,W) | mask (N,H,W) | depth (N,H,W) |
//      vt_img  (N,H,W,2) | bary (N,3,H,W) | index (N,H,W)
// ---------------------------------------------------------------------------
__global__ void k_interp(const float* __restrict__ tex,
                         const float* __restrict__ vt,
                         const int*   __restrict__ vi,
                         const int*   __restrict__ vti,
                         float* __restrict__ out)
{
    const int HW = HH * WW;
    const long long OFF_R  = 0;
    const long long OFF_M  = OFF_R  + (long long)NN * 3 * HW;
    const long long OFF_D  = OFF_M  + (long long)NN * HW;
    const long long OFF_VT = OFF_D  + (long long)NN * HW;
    const long long OFF_B  = OFF_VT + (long long)NN * HW * 2;
    const long long OFF_I  = OFF_B  + (long long)NN * 3 * HW;

    int i = blockIdx.x * blockDim.x + threadIdx.x;
    if (i >= NN * HW) return;
    int n  = i / HW;
    int hw = i % HW;
    int h  = hw / WW;
    int w  = hw % WW;

    unsigned long long key = g_key[i];
    if (key == 0xFFFFFFFFFFFFFFFFULL) {
        out[OFF_M + i] = 0.0f;
        out[OFF_D + i] = 0.0f;
        out[OFF_VT + (long long)i * 2 + 0] = 0.0f;
        out[OFF_VT + (long long)i * 2 + 1] = 0.0f;
        #pragma unroll
        for (int c = 0; c < 3; ++c) {
            out[OFF_R + (long long)(n * 3 + c) * HW + hw] = 0.0f;
            out[OFF_B + (long long)(n * 3 + c) * HW + hw] = 0.0f;
        }
        out[OFF_I + i] = -1.0f;
        return;
    }
    int idx = (int)(unsigned)(key & 0xFFFFFFFFULL);

    const float* p = g_vpix + n * NV * 3;
    int ia = vi[idx * 3 + 0], ib = vi[idx * 3 + 1], ic = vi[idx * 3 + 2];
    float x0 = p[ia * 3 + 0], y0 = p[ia * 3 + 1], z0 = p[ia * 3 + 2];
    float x1 = p[ib * 3 + 0], y1 = p[ib * 3 + 1], z1 = p[ib * 3 + 2];
    float x2 = p[ic * 3 + 0], y2 = p[ic * 3 + 1], z2 = p[ic * 3 + 2];

    float px = (float)w, py = (float)h;
    // contracted (fma) edge functions, matching XLA
    float w0 = __fmaf_rn(__fsub_rn(px, x1), __fsub_rn(y2, y1),
                         -__fmul_rn(__fsub_rn(py, y1), __fsub_rn(x2, x1)));
    float w1 = __fmaf_rn(__fsub_rn(px, x2), __fsub_rn(y0, y2),
                         -__fmul_rn(__fsub_rn(py, y2), __fsub_rn(x0, x2)));
    float w2 = __fmaf_rn(__fsub_rn(px, x0), __fsub_rn(y1, y0),
                         -__fmul_rn(__fsub_rn(py, y0), __fsub_rn(x1, x0)));
    float area = __fmaf_rn(__fsub_rn(x2, x0), __fsub_rn(y1, y0),
                           -__fmul_rn(__fsub_rn(y2, y0), __fsub_rn(x1, x0)));
    float sa = (fabsf(area) > EPSF) ? area : 1.0f;
    float b0 = __fdiv_rn(w0, sa);
    float b1 = __fdiv_rn(w1, sa);
    float b2 = __fdiv_rn(w2, sa);
    float bz0 = __fdiv_rn(b0, fmaxf(z0, EPSF));
    float bz1 = __fdiv_rn(b1, fmaxf(z1, EPSF));
    float bz2 = __fdiv_rn(b2, fmaxf(z2, EPSF));
    float zi = fmaxf(__fadd_rn(__fadd_rn(bz0, bz1), bz2), EPSF);
    float bary0 = __fdiv_rn(bz0, zi);
    float bary1 = __fdiv_rn(bz1, zi);
    float bary2 = __fdiv_rn(bz2, zi);
    float depth = __fdiv_rn(1.0f, zi);

    int ta = vti[idx * 3 + 0], tb = vti[idx * 3 + 1], tc = vti[idx * 3 + 2];
    float u0 = vt[ta * 2 + 0], v0 = __fsub_rn(1.0f, vt[ta * 2 + 1]);
    float u1 = vt[tb * 2 + 0], v1 = __fsub_rn(1.0f, vt[tb * 2 + 1]);
    float u2 = vt[tc * 2 + 0], v2 = __fsub_rn(1.0f, vt[tc * 2 + 1]);
    float vtu = __fadd_rn(__fadd_rn(__fmul_rn(bary0, u0), __fmul_rn(bary1, u1)), __fmul_rn(bary2, u2));
    float vtv = __fadd_rn(__fadd_rn(__fmul_rn(bary0, v0), __fmul_rn(bary1, v1)), __fmul_rn(bary2, v2));

    // grid sample (border padding, bilinear) on (N,3,1024,1024)
    float gx = __fsub_rn(__fmul_rn(vtu, 2.0f), 1.0f);
    float gy = __fsub_rn(__fmul_rn(vtv, 2.0f), 1.0f);
    float ix = (gx + 1.0f) * 0.5f * (float)TEXD - 0.5f;
    float iy = (gy + 1.0f) * 0.5f * (float)TEXD - 0.5f;
    float x0f = floorf(ix), y0f = floorf(iy);
    float fx = ix - x0f, fy = iy - y0f;
    int x0i = min(max((int)x0f, 0), TEXD - 1);
    int x1i = min(max((int)x0f + 1, 0), TEXD - 1);
    int y0i = min(max((int)y0f, 0), TEXD - 1);
    int y1i = min(max((int)y0f + 1, 0), TEXD - 1);

    #pragma unroll
    for (int c = 0; c < 3; ++c) {
        const float* tb_ = tex + ((long long)(n * 3 + c) * TEXD) * TEXD;
        float v00 = tb_[y0i * TEXD + x0i];
        float v01 = tb_[y0i * TEXD + x1i];
        float v10 = tb_[y1i * TEXD + x0i];
        float v11 = tb_[y1i * TEXD + x1i];
        float top = v00 * (1.0f - fx) + v01 * fx;
        float bot = v10 * (1.0f - fx) + v11 * fx;
        float val = top * (1.0f - fy) + bot * fy;
        out[OFF_R + (long long)(n * 3 + c) * HW + hw] = val;
    }

    out[OFF_M + i] = 1.0f;
    out[OFF_D + i] = depth;
    out[OFF_VT + (long long)i * 2 + 0] = vtu;
    out[OFF_VT + (long long)i * 2 + 1] = vtv;
    out[OFF_B + (long long)(n * 3 + 0) * HW + hw] = bary0;
    out[OFF_B + (long long)(n * 3 + 1) * HW + hw] = bary1;
    out[OFF_B + (long long)(n * 3 + 2) * HW + hw] = bary2;
    out[OFF_I + i] = (float)idx;
}

// ---------------------------------------------------------------------------
extern "C" void kernel_launch(void* const* d_in, const int* in_sizes, int n_in,
                              void* d_out, int out_size)
{
    const float* v       = (const float*)d_in[0];
    const float* tex     = (const float*)d_in[1];
    const float* vt      = (const float*)d_in[2];
    const int*   vi      = (const int*)  d_in[3];
    const int*   vti     = (const int*)  d_in[4];
    const float* campos  = (const float*)d_in[5];
    const float* camrot  = (const float*)d_in[6];
    const float* focal   = (const float*)d_in[7];
    const float* princpt = (const float*)d_in[8];
    float* out = (float*)d_out;

    k_project<<<(NN * NV + 255) / 256, 256>>>(v, campos, camrot, focal, princpt);
    k_trisetup<<<(NN * NF + 255) / 256, 256>>>(vi);
    k_init<<<(NN * HH * WW + 255) / 256, 256>>>();
    dim3 rgrid(NN * NF, YSPLIT);
    k_raster<<<rgrid, 128>>>();
    k_interp<<<(NN * HH * WW + 255) / 256, 256>>>(tex, vt, vi, vti, out);
}